// round 10
// baseline (speedup 1.0000x reference)
#include <cuda_runtime.h>
#include <stdint.h>

// Problem constants (match reference)
#define N_ELEMS   4194304        // total elements
#define NUM_IDS   262144
#define M_CAP     (NUM_IDS + 1)  // 262145 output rows
#define L_CAP     128
#define OUT_TOTAL (M_CAP + M_CAP * L_CAP)   // 33,816,705 floats
#define NW        264193         // full 128-float windows (NW*128 = OUT_TOTAL-1)
#define WPW       8              // windows per warp
#define NWG       33025          // warp-groups = ceil(NW / WPW)

// Scan decomposition: 512 blocks * 8192 elems; 256 threads * 32 items/thread
// (8 independent LDG.128 per thread -> MLP ~8, bandwidth-bound read)
#define NB        512
#define EPB       8192
#define BLK       256
#define IPT       32

// Scratch (device globals: no allocation allowed)
__device__ __align__(16) int   g_start[M_CAP];     // start index of run s
__device__ __align__(16) float g_idf[M_CAP];       // float(id) for written runs
__device__ __align__(16) int   g_sstart[NB * EPB]; // per-block stash: starts
__device__ __align__(16) float g_sidf[NB * EPB];   // per-block stash: float(id)
__device__ int g_block_cnt[NB];                    // runs per block
__device__ int g_num_runs;

// ---------------------------------------------------------------------------
// Kernel A: single ids read (8x LDG.128/thread, streaming); predecessor via
// shuffle/smem (no per-thread scalar global load); block-local rank scan;
// stash runs into the block's private segment. NO cross-block communication.
// ---------------------------------------------------------------------------
__global__ __launch_bounds__(BLK) void k_count_stash(const int* __restrict__ ids) {
    const int b  = blockIdx.x;
    const int t  = threadIdx.x;
    const int i0 = b * EPB + t * IPT;
    const int lane = t & 31;
    const int wid  = t >> 5;

    // 8 independent vector loads, front-batched
    const int4* p = reinterpret_cast<const int4*>(ids + i0);
    int4 a[IPT / 4];
#pragma unroll
    for (int j = 0; j < IPT / 4; j++) a[j] = __ldcs(p + j);

    int v[IPT];
#pragma unroll
    for (int j = 0; j < IPT / 4; j++) {
        v[j * 4 + 0] = a[j].x; v[j * 4 + 1] = a[j].y;
        v[j * 4 + 2] = a[j].z; v[j * 4 + 3] = a[j].w;
    }

    // predecessor value: neighbor thread's last element
    __shared__ int warp_last[BLK / 32];
    const int last  = v[IPT - 1];
    const int nprev = __shfl_up_sync(0xFFFFFFFFu, last, 1);
    if (lane == 31) warp_last[wid] = last;
    __syncthreads();
    int first_prev;
    if (t == 0)         first_prev = (b == 0) ? ~v[0] : __ldcs(ids + i0 - 1);
    else if (lane == 0) first_prev = warp_last[wid - 1];
    else                first_prev = nprev;

    // per-thread run-start count
    int prev = first_prev;
    int cnt = 0;
#pragma unroll
    for (int j = 0; j < IPT; j++) {
        cnt += (v[j] != prev);
        prev = v[j];
    }

    // block-wide exclusive scan of per-thread counts (2-level shuffle)
    int s = cnt;
#pragma unroll
    for (int off = 1; off < 32; off <<= 1) {
        int x = __shfl_up_sync(0xFFFFFFFFu, s, off);
        if (lane >= off) s += x;
    }
    __shared__ int ws[BLK / 32];
    if (lane == 31) ws[wid] = s;
    __syncthreads();
    if (wid == 0 && lane < BLK / 32) {
        int x = ws[lane];
        int y = x;
#pragma unroll
        for (int off = 1; off < BLK / 32; off <<= 1) {
            int z = __shfl_up_sync(0xFFu, y, off);
            if (lane >= off) y += z;
        }
        ws[lane] = y - x;                        // exclusive warp base
        if (lane == BLK / 32 - 1) g_block_cnt[b] = y;   // block total
    }
    __syncthreads();
    int r = ws[wid] + (s - cnt);                 // local rank within block

    // stash runs into the block's private segment
    const int seg = b * EPB;
    prev = first_prev;
#pragma unroll
    for (int j = 0; j < IPT; j++) {
        if (v[j] != prev) {
            g_sstart[seg + r] = i0 + j;
            g_sidf[seg + r]   = (float)v[j];
            r++;
        }
        prev = v[j];
    }
}

// ---------------------------------------------------------------------------
// Kernel C: block b computes base = sum(g_block_cnt[0..b-1]) directly (all
// counts final — previous kernel ended; <=2 hot-L2 loads per thread), then
// copies its stash segment to the final rank-indexed arrays.
// ---------------------------------------------------------------------------
__global__ __launch_bounds__(BLK) void k_apply() {
    const int b = blockIdx.x;
    const int t = threadIdx.x;
    const int lane = t & 31;
    const int wid  = t >> 5;

    int part = 0;
    for (int j = t; j < b; j += BLK)             // <= 2 iterations
        part += g_block_cnt[j];
#pragma unroll
    for (int off = 16; off > 0; off >>= 1)
        part += __shfl_down_sync(0xFFFFFFFFu, part, off);
    __shared__ int rs[BLK / 32];
    __shared__ int sBase;
    if (lane == 0) rs[wid] = part;
    __syncthreads();
    if (t == 0) {
        int acc = 0;
#pragma unroll
        for (int k = 0; k < BLK / 32; k++) acc += rs[k];
        sBase = acc;
    }
    __syncthreads();
    const int base = sBase;
    const int cnt  = g_block_cnt[b];

    if (b == NB - 1 && t == 0) g_num_runs = base + cnt;

    const int seg = b * EPB;
    for (int j = t; j < cnt; j += BLK) {
        g_start[base + j] = g_sstart[seg + j];
        g_idf[base + j]   = g_sidf[seg + j];
    }
}

// ---------------------------------------------------------------------------
// Kernel 2: one WARP per EIGHT consecutive 128-float output windows.
// Flat layout (float32): out[0..M_CAP) = run_ids, then padded [M_CAP x 128].
// M_CAP % 128 == 1, so window w>=2048 = col 127 of row A=w-2049 then cols
// 0..126 of row A+1 (window 2048: A=-1, head = run_ids[M_CAP-1] == -1).
// Boundary (2048) is 8-aligned: each warp-group is purely run_ids (W < 256)
// or purely padded. A padded group's 8 windows share rows A0..A0+8 -> ONE
// coalesced metadata load g_start[A0..A0+9] (lanes 0..9), then the 8 windows
// run as two register-friendly half-batches of 4.
// ---------------------------------------------------------------------------
__global__ __launch_bounds__(256) void k_fill(const float* __restrict__ feats,
                                              float* __restrict__ out) {
    if (blockIdx.x == 0 && threadIdx.x == 0)
        out[OUT_TOTAL - 1] = 0.0f;                // tail float (padding)

    const int W    = blockIdx.x * 8 + (threadIdx.x >> 5);   // warp-group id
    const int lane = threadIdx.x & 31;
    if (W >= NWG) return;
    const int w0  = W * WPW;
    const int nr1 = g_num_runs - 1;               // runs actually emitted

    if (W < 256) {
        // ---- run_ids region: 8 vectorized copies with tail masking ----
#pragma unroll
        for (int k = 0; k < WPW; k++) {
            float4 r = reinterpret_cast<const float4*>(g_idf)[(w0 + k) * 32 + lane];
            const int e = (w0 + k) * 128 + lane * 4;
            r.x = (e     < nr1) ? r.x : -1.0f;
            r.y = (e + 1 < nr1) ? r.y : -1.0f;
            r.z = (e + 2 < nr1) ? r.z : -1.0f;
            r.w = (e + 3 < nr1) ? r.w : -1.0f;
            __stcs(reinterpret_cast<float4*>(out) + (size_t)(w0 + k) * 32 + lane, r);
        }
        return;
    }

    // ---- padded region ----
    const int A0 = w0 - 2049;                     // head row of window 0

    // one coalesced metadata load: g_start[A0 .. A0+9]
    int mv = 0;
    if (lane < WPW + 2) {
        int idx = A0 + lane;
        idx = idx < 0 ? 0 : idx;
        idx = idx > nr1 ? nr1 : idx;              // clamp into written region
        mv = g_start[idx];
    }
    int m[WPW + 2];
#pragma unroll
    for (int j = 0; j < WPW + 2; j++) m[j] = __shfl_sync(0xFFFFFFFFu, mv, j);

    const int  c0 = 4 * lane - 1;                 // col of element 0
    const bool l0 = (lane == 0);

#pragma unroll
    for (int h = 0; h < 2; h++) {
        float4 r[4];
        bool   ok[4];
#pragma unroll
        for (int k2 = 0; k2 < 4; k2++) {
            const int k = h * 4 + k2;
            const int w = w0 + k;
            ok[k2] = (w < NW);
            const int A    = A0 + k;
            const int sA   = m[k];
            const int sB   = m[k + 1];
            const int sC   = m[k + 2];
            const bool vA  = ((unsigned)A       < (unsigned)nr1);
            const bool vB  = ((unsigned)(A + 1) < (unsigned)nr1);
            const int lenA = sB - sA;
            const int lenB = sC - sB;

            // element 0: lane 0 -> col 127 of row A; others -> col c0 of A+1
            const int  a0 = l0 ? (sA + 127) : (sB + c0);
            const bool p0 = l0 ? (vA && lenA > 127) : (vB && c0 < lenB);
            float x0 = (l0 && A < 0) ? -1.0f : 0.0f;
            if (ok[k2] && p0) x0 = __ldcs(feats + a0);

            float x1 = 0.0f, x2 = 0.0f, x3 = 0.0f;
            const int base = sB + c0;
            if (ok[k2] && vB && c0 + 1 < lenB) x1 = __ldcs(feats + base + 1);
            if (ok[k2] && vB && c0 + 2 < lenB) x2 = __ldcs(feats + base + 2);
            if (ok[k2] && vB && c0 + 3 < lenB) x3 = __ldcs(feats + base + 3);

            r[k2] = make_float4(x0, x1, x2, x3);
        }
#pragma unroll
        for (int k2 = 0; k2 < 4; k2++)
            if (ok[k2])
                __stcs(reinterpret_cast<float4*>(out) +
                           (size_t)(w0 + h * 4 + k2) * 32 + lane,
                       r[k2]);
    }
}

// ---------------------------------------------------------------------------
extern "C" void kernel_launch(void* const* d_in, const int* in_sizes, int n_in,
                              void* d_out, int out_size) {
    const int*   ids   = (const int*)d_in[0];
    const float* feats = (const float*)d_in[1];
    float*       out   = (float*)d_out;

    k_count_stash<<<NB, BLK>>>(ids);
    k_apply<<<NB, BLK>>>();

    const int fill_blocks = (NWG + 7) / 8;        // 8 warp-groups per block
    k_fill<<<fill_blocks, 256>>>(feats, out);
}

// round 11
// speedup vs baseline: 1.1139x; 1.1139x over previous
#include <cuda_runtime.h>
#include <stdint.h>

// Problem constants (match reference)
#define N_ELEMS   4194304        // total elements
#define N4        (N_ELEMS / 4)  // feats as float4
#define NUM_IDS   262144
#define M_CAP     (NUM_IDS + 1)  // 262145 output rows
#define L_CAP     128
#define OUT_TOTAL (M_CAP + M_CAP * L_CAP)   // 33,816,705 floats
#define NW        264193         // full 128-float windows (NW*128 = OUT_TOTAL-1)
#define WPW       8              // windows per warp
#define NWG       33025          // warp-groups = ceil(NW / WPW)

// Scan decomposition: 1024 blocks * 4096 elems; 256 threads * 16 items/thread
#define NB        1024
#define EPB       4096
#define BLK       256
#define IPT       16

// Scratch (device globals: no allocation allowed)
__device__ __align__(16) int   g_start[M_CAP];     // start index of run s
__device__ __align__(16) float g_idf[M_CAP];       // float(id) for written runs
__device__ __align__(16) int   g_sstart[NB * EPB]; // per-block stash: starts
__device__ __align__(16) float g_sidf[NB * EPB];   // per-block stash: float(id)
__device__ int g_block_cnt[NB];                    // runs per block
__device__ int g_num_runs;

// ---------------------------------------------------------------------------
// Kernel A: single ids read; block-local rank scan; stash runs into the
// block's private segment. NO cross-block communication. (R9 proven config.)
// ---------------------------------------------------------------------------
__global__ __launch_bounds__(BLK) void k_count_stash(const int* __restrict__ ids) {
    const int b  = blockIdx.x;
    const int t  = threadIdx.x;
    const int i0 = b * EPB + t * IPT;

    const int4* p = reinterpret_cast<const int4*>(ids + i0);
    int4 a0 = p[0], a1 = p[1], a2 = p[2], a3 = p[3];
    int v[IPT] = {a0.x, a0.y, a0.z, a0.w,
                  a1.x, a1.y, a1.z, a1.w,
                  a2.x, a2.y, a2.z, a2.w,
                  a3.x, a3.y, a3.z, a3.w};

    const int first_prev = (i0 == 0) ? ~v[0] : ids[i0 - 1];

    int prev = first_prev;
    int cnt = 0;
#pragma unroll
    for (int j = 0; j < IPT; j++) {
        cnt += (v[j] != prev);
        prev = v[j];
    }

    // block-wide exclusive scan of per-thread counts (2-level shuffle)
    const int lane = t & 31;
    const int wid  = t >> 5;
    int s = cnt;
#pragma unroll
    for (int off = 1; off < 32; off <<= 1) {
        int x = __shfl_up_sync(0xFFFFFFFFu, s, off);
        if (lane >= off) s += x;
    }
    __shared__ int ws[BLK / 32];
    if (lane == 31) ws[wid] = s;
    __syncthreads();
    if (wid == 0 && lane < BLK / 32) {
        int x = ws[lane];
        int y = x;
#pragma unroll
        for (int off = 1; off < BLK / 32; off <<= 1) {
            int z = __shfl_up_sync(0xFFu, y, off);
            if (lane >= off) y += z;
        }
        ws[lane] = y - x;                        // exclusive warp base
        if (lane == BLK / 32 - 1) g_block_cnt[b] = y;   // block total
    }
    __syncthreads();
    int r = ws[wid] + (s - cnt);                 // local rank within block

    const int seg = b * EPB;
    prev = first_prev;
#pragma unroll
    for (int j = 0; j < IPT; j++) {
        if (v[j] != prev) {
            g_sstart[seg + r] = i0 + j;
            g_sidf[seg + r]   = (float)v[j];
            r++;
        }
        prev = v[j];
    }
}

// ---------------------------------------------------------------------------
// Kernel C: block b computes base = sum(g_block_cnt[0..b-1]) directly (all
// counts final — previous kernel ended), then copies its stash segment to
// the final rank-indexed arrays.
// ---------------------------------------------------------------------------
__global__ __launch_bounds__(BLK) void k_apply() {
    const int b = blockIdx.x;
    const int t = threadIdx.x;
    const int lane = t & 31;
    const int wid  = t >> 5;

    int part = 0;
    for (int j = t; j < b; j += BLK)             // <= 4 iterations
        part += g_block_cnt[j];
#pragma unroll
    for (int off = 16; off > 0; off >>= 1)
        part += __shfl_down_sync(0xFFFFFFFFu, part, off);
    __shared__ int rs[BLK / 32];
    __shared__ int sBase;
    if (lane == 0) rs[wid] = part;
    __syncthreads();
    if (t == 0) {
        int acc = 0;
#pragma unroll
        for (int k = 0; k < BLK / 32; k++) acc += rs[k];
        sBase = acc;
    }
    __syncthreads();
    const int base = sBase;
    const int cnt  = g_block_cnt[b];

    if (b == NB - 1 && t == 0) g_num_runs = base + cnt;

    const int seg = b * EPB;
    for (int j = t; j < cnt; j += BLK) {
        g_start[base + j] = g_sstart[seg + j];
        g_idf[base + j]   = g_sidf[seg + j];
    }
}

// ---------------------------------------------------------------------------
// Kernel 2: one WARP per EIGHT consecutive 128-float output windows.
// Flat layout (float32): out[0..M_CAP) = run_ids, then padded [M_CAP x 128].
// M_CAP % 128 == 1: window w>=2048 = col 127 of row A=w-2049 then cols
// 0..126 of row B=A+1 (window 2048: A=-1, head = run_ids[M_CAP-1] == -1).
//
// NEW: the per-window feats span is ONE contiguous 512B block
// [sB-off, sB-off+128) with off = sB & 3. Each lane does one aligned
// LDG.128 (V), then realigns in-register via 0-2 warp shuffles keyed by the
// warp-uniform off (4-way uniform switch). Lane-0 head element (col 127 of
// row A) is one predicated scalar load. This cuts L1 load wavefronts ~3x
// and removes the 3x-redundant sector refetch of the old scalar gathers.
// ---------------------------------------------------------------------------
__global__ __launch_bounds__(256) void k_fill(const float* __restrict__ feats,
                                              float* __restrict__ out) {
    if (blockIdx.x == 0 && threadIdx.x == 0)
        out[OUT_TOTAL - 1] = 0.0f;                // tail float (padding)

    const int W    = blockIdx.x * 8 + (threadIdx.x >> 5);   // warp-group id
    const int lane = threadIdx.x & 31;
    if (W >= NWG) return;
    const int w0  = W * WPW;
    const int nr1 = g_num_runs - 1;               // runs actually emitted

    if (W < 256) {
        // ---- run_ids region: 8 vectorized copies with tail masking ----
#pragma unroll
        for (int k = 0; k < WPW; k++) {
            float4 r = reinterpret_cast<const float4*>(g_idf)[(w0 + k) * 32 + lane];
            const int e = (w0 + k) * 128 + lane * 4;
            r.x = (e     < nr1) ? r.x : -1.0f;
            r.y = (e + 1 < nr1) ? r.y : -1.0f;
            r.z = (e + 2 < nr1) ? r.z : -1.0f;
            r.w = (e + 3 < nr1) ? r.w : -1.0f;
            __stcs(reinterpret_cast<float4*>(out) + (size_t)(w0 + k) * 32 + lane, r);
        }
        return;
    }

    // ---- padded region ----
    const int A0 = w0 - 2049;                     // head row of window 0

    // one coalesced metadata load: g_start[A0 .. A0+9]
    int mv = 0;
    if (lane < WPW + 2) {
        int idx = A0 + lane;
        idx = idx < 0 ? 0 : idx;
        idx = idx > nr1 ? nr1 : idx;              // clamp into written region
        mv = g_start[idx];
    }
    int m[WPW + 2];
#pragma unroll
    for (int j = 0; j < WPW + 2; j++) m[j] = __shfl_sync(0xFFFFFFFFu, mv, j);

    const bool l0 = (lane == 0);
    const int  c0 = 4 * lane - 1;                 // col of element 0

#pragma unroll
    for (int h = 0; h < 2; h++) {
        float4 V[4];
        float  head[4];
        int    offk[4];
        bool   okk[4], vBk[4];
        int    lenBk[4];

        // --- batched loads for 4 windows (MLP) ---
#pragma unroll
        for (int k2 = 0; k2 < 4; k2++) {
            const int k  = h * 4 + k2;
            const int w  = w0 + k;
            okk[k2] = (w < NW);
            const int A    = A0 + k;
            const int sA   = m[k];
            const int sB   = m[k + 1];
            const int sC   = m[k + 2];
            const bool vA  = ((unsigned)A       < (unsigned)nr1);
            vBk[k2]        = ((unsigned)(A + 1) < (unsigned)nr1);
            const int lenA = sB - sA;
            lenBk[k2]      = sC - sB;
            offk[k2]       = sB & 3;

            // whole-window vector load (clamped; garbage masked later)
            int q = (sB >> 2) + lane;
            q = q < N4 - 1 ? q : N4 - 1;
            V[k2] = make_float4(0.f, 0.f, 0.f, 0.f);
            if (okk[k2] && vBk[k2])
                V[k2] = __ldcs(reinterpret_cast<const float4*>(feats) + q);

            // head element (lane 0): col 127 of row A
            head[k2] = (A < 0) ? -1.0f : 0.0f;
            if (okk[k2] && l0 && vA && lenA > 127)
                head[k2] = __ldcs(feats + sA + 127);
        }

        // --- realign + mask + store per window ---
#pragma unroll
        for (int k2 = 0; k2 < 4; k2++) {
            const int off  = offk[k2];
            const int lenB = lenBk[k2];
            const bool vB  = vBk[k2];
            float e0, e1, e2, e3;

            // warp-uniform 4-way select on off
            if (off == 1) {
                e0 = V[k2].x; e1 = V[k2].y; e2 = V[k2].z; e3 = V[k2].w;
            } else if (off == 0) {
                const float pw = __shfl_up_sync(0xFFFFFFFFu, V[k2].w, 1);
                e0 = pw;      e1 = V[k2].x; e2 = V[k2].y; e3 = V[k2].z;
            } else if (off == 2) {
                const float nx = __shfl_down_sync(0xFFFFFFFFu, V[k2].x, 1);
                e0 = V[k2].y; e1 = V[k2].z; e2 = V[k2].w; e3 = nx;
            } else {
                const float nx = __shfl_down_sync(0xFFFFFFFFu, V[k2].x, 1);
                const float ny = __shfl_down_sync(0xFFFFFFFFu, V[k2].y, 1);
                e0 = V[k2].z; e1 = V[k2].w; e2 = nx;      e3 = ny;
            }

            // masks: element i is col c0+i of row B (lane0 e0 = head)
            e0 = (vB && c0     >= 0 && c0     < lenB) ? e0 : 0.0f;
            e1 = (vB && c0 + 1 < lenB) ? e1 : 0.0f;
            e2 = (vB && c0 + 2 < lenB) ? e2 : 0.0f;
            e3 = (vB && c0 + 3 < lenB) ? e3 : 0.0f;
            if (l0) e0 = head[k2];

            if (okk[k2])
                __stcs(reinterpret_cast<float4*>(out) +
                           (size_t)(w0 + h * 4 + k2) * 32 + lane,
                       make_float4(e0, e1, e2, e3));
        }
    }
}

// ---------------------------------------------------------------------------
extern "C" void kernel_launch(void* const* d_in, const int* in_sizes, int n_in,
                              void* d_out, int out_size) {
    const int*   ids   = (const int*)d_in[0];
    const float* feats = (const float*)d_in[1];
    float*       out   = (float*)d_out;

    k_count_stash<<<NB, BLK>>>(ids);
    k_apply<<<NB, BLK>>>();

    const int fill_blocks = (NWG + 7) / 8;        // 8 warp-groups per block
    k_fill<<<fill_blocks, 256>>>(feats, out);
}

// round 12
// speedup vs baseline: 1.1635x; 1.0445x over previous
#include <cuda_runtime.h>
#include <stdint.h>

// Problem constants (match reference)
#define N_ELEMS   4194304        // total elements
#define N4        (N_ELEMS / 4)  // feats as float4
#define NUM_IDS   262144
#define M_CAP     (NUM_IDS + 1)  // 262145 output rows
#define L_CAP     128
#define OUT_TOTAL (M_CAP + M_CAP * L_CAP)   // 33,816,705 floats
#define NW        264193         // full 128-float windows (NW*128 = OUT_TOTAL-1)
#define WPW       8              // windows per warp
#define NWG       33025          // warp-groups = ceil(NW / WPW)

// Scan decomposition: 1024 blocks * 4096 elems; 256 threads * 16 items/thread
#define NB        1024
#define EPB       4096
#define BLK       256
#define IPT       16

// Scratch (device globals: no allocation allowed)
__device__ __align__(16) int   g_start[M_CAP];     // start index of run s
__device__ __align__(16) float g_idf[M_CAP];       // float(id) for written runs
__device__ __align__(16) int   g_sstart[NB * EPB]; // per-block stash: starts
__device__ __align__(16) float g_sidf[NB * EPB];   // per-block stash: float(id)
__device__ int g_block_cnt[NB];                    // runs per block
__device__ int g_num_runs;

// ---------------------------------------------------------------------------
// Kernel A: single ids read; boundary BITMASK (popc count, ffs scatter —
// avg 1 set bit per thread instead of a 16-iteration predicated store loop);
// block-local rank scan; stash runs into the block's private segment.
// NO cross-block communication. __launch_bounds__(256,8) -> 8 blocks/SM.
// ---------------------------------------------------------------------------
__global__ __launch_bounds__(BLK, 8) void k_count_stash(const int* __restrict__ ids) {
    const int b  = blockIdx.x;
    const int t  = threadIdx.x;
    const int i0 = b * EPB + t * IPT;

    const int4* p = reinterpret_cast<const int4*>(ids + i0);
    int4 a0 = p[0], a1 = p[1], a2 = p[2], a3 = p[3];
    int v[IPT] = {a0.x, a0.y, a0.z, a0.w,
                  a1.x, a1.y, a1.z, a1.w,
                  a2.x, a2.y, a2.z, a2.w,
                  a3.x, a3.y, a3.z, a3.w};

    const int first_prev = (i0 == 0) ? ~v[0] : ids[i0 - 1];

    // boundary bitmask
    unsigned bm = 0;
    int prev = first_prev;
#pragma unroll
    for (int j = 0; j < IPT; j++) {
        bm |= (unsigned)(v[j] != prev) << j;
        prev = v[j];
    }
    const int cnt = __popc(bm);

    // block-wide exclusive scan of per-thread counts (2-level shuffle)
    const int lane = t & 31;
    const int wid  = t >> 5;
    int s = cnt;
#pragma unroll
    for (int off = 1; off < 32; off <<= 1) {
        int x = __shfl_up_sync(0xFFFFFFFFu, s, off);
        if (lane >= off) s += x;
    }
    __shared__ int ws[BLK / 32];
    if (lane == 31) ws[wid] = s;
    __syncthreads();
    if (wid == 0 && lane < BLK / 32) {
        int x = ws[lane];
        int y = x;
#pragma unroll
        for (int off = 1; off < BLK / 32; off <<= 1) {
            int z = __shfl_up_sync(0xFFu, y, off);
            if (lane >= off) y += z;
        }
        ws[lane] = y - x;                        // exclusive warp base
        if (lane == BLK / 32 - 1) g_block_cnt[b] = y;   // block total
    }
    __syncthreads();
    int r = ws[wid] + (s - cnt);                 // local rank within block

    // scatter ONLY set bits (avg 1 per thread). Value reloaded via ids[]:
    // the line is L1-resident (just loaded non-streaming), and this avoids
    // a dynamic index into v[] which would spill it to local memory.
    const int seg = b * EPB;
    while (bm) {
        const int j = __ffs(bm) - 1;
        bm &= bm - 1;
        g_sstart[seg + r] = i0 + j;
        g_sidf[seg + r]   = (float)ids[i0 + j];
        r++;
    }
}

// ---------------------------------------------------------------------------
// Kernel C: block b computes base = sum(g_block_cnt[0..b-1]) directly (all
// counts final — previous kernel ended), then copies its stash segment to
// the final rank-indexed arrays.
// ---------------------------------------------------------------------------
__global__ __launch_bounds__(BLK) void k_apply() {
    const int b = blockIdx.x;
    const int t = threadIdx.x;
    const int lane = t & 31;
    const int wid  = t >> 5;

    int part = 0;
    for (int j = t; j < b; j += BLK)             // <= 4 iterations
        part += g_block_cnt[j];
#pragma unroll
    for (int off = 16; off > 0; off >>= 1)
        part += __shfl_down_sync(0xFFFFFFFFu, part, off);
    __shared__ int rs[BLK / 32];
    __shared__ int sBase;
    if (lane == 0) rs[wid] = part;
    __syncthreads();
    if (t == 0) {
        int acc = 0;
#pragma unroll
        for (int k = 0; k < BLK / 32; k++) acc += rs[k];
        sBase = acc;
    }
    __syncthreads();
    const int base = sBase;
    const int cnt  = g_block_cnt[b];

    if (b == NB - 1 && t == 0) g_num_runs = base + cnt;

    const int seg = b * EPB;
    for (int j = t; j < cnt; j += BLK) {
        g_start[base + j] = g_sstart[seg + j];
        g_idf[base + j]   = g_sidf[seg + j];
    }
}

// ---------------------------------------------------------------------------
// Kernel 2: one WARP per EIGHT consecutive 128-float output windows.
// Flat layout (float32): out[0..M_CAP) = run_ids, then padded [M_CAP x 128].
// M_CAP % 128 == 1: window w>=2048 = col 127 of row A=w-2049 then cols
// 0..126 of row B=A+1 (window 2048: A=-1, head = run_ids[M_CAP-1] == -1).
// Per-window feats span is ONE contiguous 512B block [sB-off, sB-off+128),
// off = sB & 3: one aligned LDG.128 per lane + 0-2 warp shuffles keyed by
// the warp-uniform off. Lane-0 head (col 127 of row A) is one predicated
// scalar load. (R11 proven version.)
// ---------------------------------------------------------------------------
__global__ __launch_bounds__(256) void k_fill(const float* __restrict__ feats,
                                              float* __restrict__ out) {
    if (blockIdx.x == 0 && threadIdx.x == 0)
        out[OUT_TOTAL - 1] = 0.0f;                // tail float (padding)

    const int W    = blockIdx.x * 8 + (threadIdx.x >> 5);   // warp-group id
    const int lane = threadIdx.x & 31;
    if (W >= NWG) return;
    const int w0  = W * WPW;
    const int nr1 = g_num_runs - 1;               // runs actually emitted

    if (W < 256) {
        // ---- run_ids region: 8 vectorized copies with tail masking ----
#pragma unroll
        for (int k = 0; k < WPW; k++) {
            float4 r = reinterpret_cast<const float4*>(g_idf)[(w0 + k) * 32 + lane];
            const int e = (w0 + k) * 128 + lane * 4;
            r.x = (e     < nr1) ? r.x : -1.0f;
            r.y = (e + 1 < nr1) ? r.y : -1.0f;
            r.z = (e + 2 < nr1) ? r.z : -1.0f;
            r.w = (e + 3 < nr1) ? r.w : -1.0f;
            __stcs(reinterpret_cast<float4*>(out) + (size_t)(w0 + k) * 32 + lane, r);
        }
        return;
    }

    // ---- padded region ----
    const int A0 = w0 - 2049;                     // head row of window 0

    // one coalesced metadata load: g_start[A0 .. A0+9]
    int mv = 0;
    if (lane < WPW + 2) {
        int idx = A0 + lane;
        idx = idx < 0 ? 0 : idx;
        idx = idx > nr1 ? nr1 : idx;              // clamp into written region
        mv = g_start[idx];
    }
    int m[WPW + 2];
#pragma unroll
    for (int j = 0; j < WPW + 2; j++) m[j] = __shfl_sync(0xFFFFFFFFu, mv, j);

    const bool l0 = (lane == 0);
    const int  c0 = 4 * lane - 1;                 // col of element 0

#pragma unroll
    for (int h = 0; h < 2; h++) {
        float4 V[4];
        float  head[4];
        int    offk[4];
        bool   okk[4], vBk[4];
        int    lenBk[4];

        // --- batched loads for 4 windows (MLP) ---
#pragma unroll
        for (int k2 = 0; k2 < 4; k2++) {
            const int k  = h * 4 + k2;
            const int w  = w0 + k;
            okk[k2] = (w < NW);
            const int A    = A0 + k;
            const int sA   = m[k];
            const int sB   = m[k + 1];
            const int sC   = m[k + 2];
            const bool vA  = ((unsigned)A       < (unsigned)nr1);
            vBk[k2]        = ((unsigned)(A + 1) < (unsigned)nr1);
            const int lenA = sB - sA;
            lenBk[k2]      = sC - sB;
            offk[k2]       = sB & 3;

            int q = (sB >> 2) + lane;
            q = q < N4 - 1 ? q : N4 - 1;
            V[k2] = make_float4(0.f, 0.f, 0.f, 0.f);
            if (okk[k2] && vBk[k2])
                V[k2] = __ldcs(reinterpret_cast<const float4*>(feats) + q);

            head[k2] = (A < 0) ? -1.0f : 0.0f;
            if (okk[k2] && l0 && vA && lenA > 127)
                head[k2] = __ldcs(feats + sA + 127);
        }

        // --- realign + mask + store per window ---
#pragma unroll
        for (int k2 = 0; k2 < 4; k2++) {
            const int off  = offk[k2];
            const int lenB = lenBk[k2];
            const bool vB  = vBk[k2];
            float e0, e1, e2, e3;

            if (off == 1) {
                e0 = V[k2].x; e1 = V[k2].y; e2 = V[k2].z; e3 = V[k2].w;
            } else if (off == 0) {
                const float pw = __shfl_up_sync(0xFFFFFFFFu, V[k2].w, 1);
                e0 = pw;      e1 = V[k2].x; e2 = V[k2].y; e3 = V[k2].z;
            } else if (off == 2) {
                const float nx = __shfl_down_sync(0xFFFFFFFFu, V[k2].x, 1);
                e0 = V[k2].y; e1 = V[k2].z; e2 = V[k2].w; e3 = nx;
            } else {
                const float nx = __shfl_down_sync(0xFFFFFFFFu, V[k2].x, 1);
                const float ny = __shfl_down_sync(0xFFFFFFFFu, V[k2].y, 1);
                e0 = V[k2].z; e1 = V[k2].w; e2 = nx;      e3 = ny;
            }

            e0 = (vB && c0     >= 0 && c0     < lenB) ? e0 : 0.0f;
            e1 = (vB && c0 + 1 < lenB) ? e1 : 0.0f;
            e2 = (vB && c0 + 2 < lenB) ? e2 : 0.0f;
            e3 = (vB && c0 + 3 < lenB) ? e3 : 0.0f;
            if (l0) e0 = head[k2];

            if (okk[k2])
                __stcs(reinterpret_cast<float4*>(out) +
                           (size_t)(w0 + h * 4 + k2) * 32 + lane,
                       make_float4(e0, e1, e2, e3));
        }
    }
}

// ---------------------------------------------------------------------------
extern "C" void kernel_launch(void* const* d_in, const int* in_sizes, int n_in,
                              void* d_out, int out_size) {
    const int*   ids   = (const int*)d_in[0];
    const float* feats = (const float*)d_in[1];
    float*       out   = (float*)d_out;

    k_count_stash<<<NB, BLK>>>(ids);
    k_apply<<<NB, BLK>>>();

    const int fill_blocks = (NWG + 7) / 8;        // 8 warp-groups per block
    k_fill<<<fill_blocks, 256>>>(feats, out);
}